// round 1
// baseline (speedup 1.0000x reference)
#include <cuda_runtime.h>
#include <cuda_bf16.h>
#include <cstdint>
#include <cstddef>

// Problem constants
#define BB 32
#define NN 4096
#define CC 768
#define KK 8
#define MM (BB * NN)   // 131072 rows

// Scratch (allocation-free rule: __device__ globals)
__device__ float g_mu[MM];
__device__ float g_rstd[MM];
__device__ float g_logits[(size_t)MM * KK];

// ---------------------------------------------------------------------------
// Kernel 1: LayerNorm statistics. One warp per row.
// ---------------------------------------------------------------------------
__global__ __launch_bounds__(256)
void ln_stats_kernel(const float* __restrict__ x) {
    const int row = blockIdx.x * 8 + (threadIdx.x >> 5);
    const int lane = threadIdx.x & 31;
    if (row >= MM) return;
    const float4* r = (const float4*)(x + (size_t)row * CC);
    float s = 0.f, ss = 0.f;
    #pragma unroll
    for (int i = lane; i < CC / 4; i += 32) {
        float4 v = r[i];
        s  += v.x + v.y + v.z + v.w;
        ss += v.x * v.x + v.y * v.y + v.z * v.z + v.w * v.w;
    }
    #pragma unroll
    for (int o = 16; o; o >>= 1) {
        s  += __shfl_xor_sync(0xffffffffu, s,  o);
        ss += __shfl_xor_sync(0xffffffffu, ss, o);
    }
    if (lane == 0) {
        float mu  = s * (1.0f / CC);
        float var = ss * (1.0f / CC) - mu * mu;
        g_mu[row]   = mu;
        g_rstd[row] = rsqrtf(var + 1e-5f);
    }
}

// ---------------------------------------------------------------------------
// Kernel 2: fused  logits = GELU(LN(x) @ W1 + b1) @ W2 + b2
// Block: 128 rows, loops over 6 column tiles of 128; h1 never hits global mem.
// ---------------------------------------------------------------------------
__device__ __forceinline__ float gelu_exact(float v) {
    return 0.5f * v * (1.0f + erff(v * 0.70710678118654752440f));
}

__global__ __launch_bounds__(256, 2)
void fused_mlp_kernel(const float* __restrict__ x,
                      const float* __restrict__ gamma,
                      const float* __restrict__ beta,
                      const float* __restrict__ W1,
                      const float* __restrict__ b1,
                      const float* __restrict__ W2,
                      const float* __restrict__ b2) {
    __shared__ float As[2][8][128];
    __shared__ float Bs[2][8][128];
    __shared__ float W2s[128 * 8];
    __shared__ float logits_s[128][8];
    __shared__ float gs[CC], bs[CC], b1s[CC];

    const int tid = threadIdx.x;
    const int row_base = blockIdx.x * 128;

    for (int i = tid; i < CC; i += 256) { gs[i] = gamma[i]; bs[i] = beta[i]; b1s[i] = b1[i]; }
    for (int i = tid; i < 128 * 8; i += 256) ((float*)logits_s)[i] = 0.f;

    // A-load assignment: 2 threads per row, one float4 (4 k's) each
    const int arow = tid >> 1;
    const int avec = (tid & 1) * 4;
    const float mu_r = g_mu[row_base + arow];
    const float rs_r = g_rstd[row_base + arow];
    const float* xrow = x + (size_t)(row_base + arow) * CC;

    // B-load assignment: Bs[bk][bj..bj+3]
    const int bk = tid >> 5;
    const int bj = (tid & 31) * 4;

    // compute microtile: 8x8 per thread, 16x16 thread grid
    const int tx = (tid & 15) * 8;
    const int ty = (tid >> 4) * 8;

    __syncthreads();

    for (int jt = 0; jt < 6; ++jt) {
        const int jbase = jt * 128;

        // stage W2 slice [128 cols x 8] (contiguous in W2 row-major [C][8])
        {
            float4 w = *(const float4*)(W2 + (size_t)jbase * 8 + tid * 4);
            *(float4*)(W2s + tid * 4) = w;
        }

        float acc[8][8];
        #pragma unroll
        for (int i = 0; i < 8; ++i)
            #pragma unroll
            for (int j = 0; j < 8; ++j) acc[i][j] = 0.f;

        // prologue: chunk 0 into buffer 0
        {
            float4 a = *(const float4*)(xrow + avec);
            float4 b = *(const float4*)(W1 + (size_t)bk * CC + jbase + bj);
            const int k = avec;
            As[0][k + 0][arow] = ((a.x - mu_r) * rs_r) * gs[k + 0] + bs[k + 0];
            As[0][k + 1][arow] = ((a.y - mu_r) * rs_r) * gs[k + 1] + bs[k + 1];
            As[0][k + 2][arow] = ((a.z - mu_r) * rs_r) * gs[k + 2] + bs[k + 2];
            As[0][k + 3][arow] = ((a.w - mu_r) * rs_r) * gs[k + 3] + bs[k + 3];
            *(float4*)(&Bs[0][bk][bj]) = b;
        }
        __syncthreads();

        int buf = 0;
        for (int kc = 0; kc < 96; ++kc) {
            float4 aN, bN;
            const int k0n = (kc + 1) * 8;
            if (kc < 95) {
                aN = *(const float4*)(xrow + k0n + avec);
                bN = *(const float4*)(W1 + (size_t)(k0n + bk) * CC + jbase + bj);
            }
            // compute on current buffer
            #pragma unroll
            for (int k = 0; k < 8; ++k) {
                float a[8], bfr[8];
                *(float4*)(a)       = *(const float4*)(&As[buf][k][ty]);
                *(float4*)(a + 4)   = *(const float4*)(&As[buf][k][ty + 4]);
                *(float4*)(bfr)     = *(const float4*)(&Bs[buf][k][tx]);
                *(float4*)(bfr + 4) = *(const float4*)(&Bs[buf][k][tx + 4]);
                #pragma unroll
                for (int i = 0; i < 8; ++i)
                    #pragma unroll
                    for (int j = 0; j < 8; ++j)
                        acc[i][j] = fmaf(a[i], bfr[j], acc[i][j]);
            }
            if (kc < 95) {
                const int kg = k0n + avec;
                const int kb = avec;
                As[buf ^ 1][kb + 0][arow] = ((aN.x - mu_r) * rs_r) * gs[kg + 0] + bs[kg + 0];
                As[buf ^ 1][kb + 1][arow] = ((aN.y - mu_r) * rs_r) * gs[kg + 1] + bs[kg + 1];
                As[buf ^ 1][kb + 2][arow] = ((aN.z - mu_r) * rs_r) * gs[kg + 2] + bs[kg + 2];
                As[buf ^ 1][kb + 3][arow] = ((aN.w - mu_r) * rs_r) * gs[kg + 3] + bs[kg + 3];
                *(float4*)(&Bs[buf ^ 1][bk][bj]) = bN;
            }
            __syncthreads();
            buf ^= 1;
        }

        // epilogue: GELU then fold through W2 into shared logits accumulator
        #pragma unroll
        for (int i = 0; i < 8; ++i) {
            const int r = ty + i;
            float h[8];
            #pragma unroll
            for (int j = 0; j < 8; ++j)
                h[j] = gelu_exact(acc[i][j] + b1s[jbase + tx + j]);
            #pragma unroll
            for (int kk = 0; kk < 8; ++kk) {
                float s = 0.f;
                #pragma unroll
                for (int j = 0; j < 8; ++j)
                    s = fmaf(h[j], W2s[(tx + j) * 8 + kk], s);
                atomicAdd(&logits_s[r][kk], s);
            }
        }
        __syncthreads();
    }

    for (int i = tid; i < 128 * 8; i += 256) {
        const int r = i >> 3, kk = i & 7;
        g_logits[(size_t)(row_base + r) * KK + kk] = logits_s[r][kk] + __ldg(&b2[kk]);
    }
}

// ---------------------------------------------------------------------------
// Kernel 3: softmax over tokens (dim N) per (b,k). One block per (b,k).
// In-place on g_logits.
// ---------------------------------------------------------------------------
__global__ __launch_bounds__(256)
void softmax_kernel() {
    __shared__ float red[8];
    __shared__ float bcast;
    const int b  = blockIdx.x >> 3;
    const int kk = blockIdx.x & 7;
    const int tid = threadIdx.x;
    float* base = g_logits + (size_t)b * NN * KK + kk;

    float v[16];
    float mx = -1e30f;
    #pragma unroll
    for (int i = 0; i < 16; ++i) {
        v[i] = base[(size_t)(i * 256 + tid) * KK];
        mx = fmaxf(mx, v[i]);
    }
    #pragma unroll
    for (int o = 16; o; o >>= 1) mx = fmaxf(mx, __shfl_xor_sync(0xffffffffu, mx, o));
    if ((tid & 31) == 0) red[tid >> 5] = mx;
    __syncthreads();
    if (tid < 32) {
        float m = (tid < 8) ? red[tid] : -1e30f;
        #pragma unroll
        for (int o = 4; o; o >>= 1) m = fmaxf(m, __shfl_xor_sync(0xffffffffu, m, o));
        if (tid == 0) bcast = m;
    }
    __syncthreads();
    mx = bcast;

    float s = 0.f;
    #pragma unroll
    for (int i = 0; i < 16; ++i) {
        v[i] = __expf(v[i] - mx);
        s += v[i];
    }
    #pragma unroll
    for (int o = 16; o; o >>= 1) s += __shfl_xor_sync(0xffffffffu, s, o);
    __syncthreads();
    if ((tid & 31) == 0) red[tid >> 5] = s;
    __syncthreads();
    if (tid < 32) {
        float t = (tid < 8) ? red[tid] : 0.f;
        #pragma unroll
        for (int o = 4; o; o >>= 1) t += __shfl_xor_sync(0xffffffffu, t, o);
        if (tid == 0) bcast = t;
    }
    __syncthreads();
    const float inv = 1.0f / bcast;
    #pragma unroll
    for (int i = 0; i < 16; ++i)
        base[(size_t)(i * 256 + tid) * KK] = v[i] * inv;
}

// ---------------------------------------------------------------------------
// Kernel 4: out[b,k,c] = sum_n attn[b,n,k] * x[b,n,c]
// grid (nsplit=4, ctile=3, b=32); atomicAdd into pre-zeroed out.
// ---------------------------------------------------------------------------
__global__ __launch_bounds__(256)
void pool_kernel(const float* __restrict__ x, float* __restrict__ out) {
    __shared__ float attn_s[1024][8];   // 32 KB
    const int nc = blockIdx.x;          // 0..3
    const int ct = blockIdx.y;          // 0..2
    const int b  = blockIdx.z;          // 0..31
    const int n0 = nc * 1024;

    const float* lp = g_logits + ((size_t)b * NN + n0) * KK;
    for (int i = threadIdx.x; i < 1024 * 8 / 4; i += 256)
        ((float4*)attn_s)[i] = ((const float4*)lp)[i];
    __syncthreads();

    const int c = ct * 256 + threadIdx.x;
    const float* xp = x + ((size_t)b * NN + n0) * CC + c;
    float acc[8];
    #pragma unroll
    for (int kk = 0; kk < 8; ++kk) acc[kk] = 0.f;

    #pragma unroll 4
    for (int n = 0; n < 1024; ++n) {
        const float xv = xp[(size_t)n * CC];
        float4 a0 = *(const float4*)(&attn_s[n][0]);
        float4 a1 = *(const float4*)(&attn_s[n][4]);
        acc[0] = fmaf(a0.x, xv, acc[0]);
        acc[1] = fmaf(a0.y, xv, acc[1]);
        acc[2] = fmaf(a0.z, xv, acc[2]);
        acc[3] = fmaf(a0.w, xv, acc[3]);
        acc[4] = fmaf(a1.x, xv, acc[4]);
        acc[5] = fmaf(a1.y, xv, acc[5]);
        acc[6] = fmaf(a1.z, xv, acc[6]);
        acc[7] = fmaf(a1.w, xv, acc[7]);
    }
    #pragma unroll
    for (int kk = 0; kk < 8; ++kk)
        atomicAdd(&out[((size_t)b * KK + kk) * CC + c], acc[kk]);
}

// ---------------------------------------------------------------------------
extern "C" void kernel_launch(void* const* d_in, const int* in_sizes, int n_in,
                              void* d_out, int out_size) {
    const float* x     = (const float*)d_in[0];
    const float* gamma = (const float*)d_in[1];
    const float* beta  = (const float*)d_in[2];
    const float* W1    = (const float*)d_in[3];
    const float* b1    = (const float*)d_in[4];
    const float* W2    = (const float*)d_in[5];
    const float* b2    = (const float*)d_in[6];
    float* out = (float*)d_out;

    cudaMemsetAsync(out, 0, (size_t)out_size * sizeof(float));
    ln_stats_kernel<<<MM / 8, 256>>>(x);
    fused_mlp_kernel<<<MM / 128, 256>>>(x, gamma, beta, W1, b1, W2, b2);
    softmax_kernel<<<BB * KK, 256>>>();
    pool_kernel<<<dim3(4, 3, 32), 256>>>(x, out);
}

// round 4
// speedup vs baseline: 3.5204x; 3.5204x over previous
#include <cuda_runtime.h>
#include <cuda_bf16.h>
#include <cstdint>
#include <cstddef>

#define BB 32
#define NN 4096
#define CC 768
#define KK 8
#define MM (BB * NN)   // 131072 rows

// Scratch (__device__ globals; allocation-free rule)
__device__ __nv_bfloat16 g_Ahi[(size_t)MM * CC];   // LN(x) hi, bf16
__device__ __nv_bfloat16 g_Alo[(size_t)MM * CC];   // LN(x) lo, bf16
__device__ __nv_bfloat16 g_W1Thi[(size_t)CC * CC]; // W1^T hi ([n][k], k contiguous)
__device__ __nv_bfloat16 g_W1Tlo[(size_t)CC * CC];
__device__ float g_logits[(size_t)MM * KK];

// ---------------------------------------------------------------------------
// PTX helpers (all plain-sm_103-legal: mma.sync, ldmatrix, cp.async)
// ---------------------------------------------------------------------------
__device__ __forceinline__ uint32_t smem_to_u32(const void* p) {
    uint32_t a;
    asm("{ .reg .u64 t; cvta.to.shared.u64 t, %1; cvt.u32.u64 %0, t; }"
        : "=r"(a) : "l"(p));
    return a;
}
#define CP_ASYNC16(dst, src) \
    asm volatile("cp.async.cg.shared.global [%0], [%1], 16;" :: "r"(dst), "l"(src))
#define CP_COMMIT() asm volatile("cp.async.commit_group;" ::: "memory")
#define CP_WAIT(n)  asm volatile("cp.async.wait_group %0;" :: "n"(n) : "memory")

__device__ __forceinline__ void ldsm_x4(uint32_t (&r)[4], uint32_t addr) {
    asm volatile("ldmatrix.sync.aligned.m8n8.x4.shared.b16 {%0,%1,%2,%3}, [%4];"
        : "=r"(r[0]), "=r"(r[1]), "=r"(r[2]), "=r"(r[3]) : "r"(addr));
}
__device__ __forceinline__ void mma_bf16(float (&d)[4], const uint32_t (&a)[4],
                                         const uint32_t* b) {
    asm volatile(
        "mma.sync.aligned.m16n8k16.row.col.f32.bf16.bf16.f32 "
        "{%0,%1,%2,%3}, {%4,%5,%6,%7}, {%8,%9}, {%0,%1,%2,%3};"
        : "+f"(d[0]), "+f"(d[1]), "+f"(d[2]), "+f"(d[3])
        : "r"(a[0]), "r"(a[1]), "r"(a[2]), "r"(a[3]), "r"(b[0]), "r"(b[1]));
}

__device__ __forceinline__ float gelu_exact(float v) {
    return 0.5f * v * (1.0f + erff(v * 0.70710678118654752440f));
}

// ---------------------------------------------------------------------------
// Kernel 1: fused LN stats + bf16 hi/lo split. One warp per row. Zeroes logits.
// ---------------------------------------------------------------------------
__global__ __launch_bounds__(256)
void ln_convert_kernel(const float* __restrict__ x,
                       const float* __restrict__ gamma,
                       const float* __restrict__ beta) {
    __shared__ float gs[CC], bs[CC];
    const int tid = threadIdx.x;
    for (int i = tid; i < CC; i += 256) { gs[i] = gamma[i]; bs[i] = beta[i]; }
    if (blockIdx.x < (MM * KK) / 256)
        g_logits[(size_t)blockIdx.x * 256 + tid] = 0.f;
    __syncthreads();

    const int row  = blockIdx.x * 8 + (tid >> 5);
    const int lane = tid & 31;
    const float4* r = (const float4*)(x + (size_t)row * CC);
    float s = 0.f, ss = 0.f;
    #pragma unroll
    for (int i = lane; i < CC / 4; i += 32) {
        float4 v = r[i];
        s  += v.x + v.y + v.z + v.w;
        ss += v.x * v.x + v.y * v.y + v.z * v.z + v.w * v.w;
    }
    #pragma unroll
    for (int o = 16; o; o >>= 1) {
        s  += __shfl_xor_sync(0xffffffffu, s,  o);
        ss += __shfl_xor_sync(0xffffffffu, ss, o);
    }
    const float mu = s * (1.0f / CC);
    const float rs = rsqrtf(ss * (1.0f / CC) - mu * mu + 1e-5f);

    __nv_bfloat16* ah = g_Ahi + (size_t)row * CC;
    __nv_bfloat16* al = g_Alo + (size_t)row * CC;
    #pragma unroll
    for (int i = lane; i < CC / 4; i += 32) {
        float4 v = r[i];
        float y[4] = {v.x, v.y, v.z, v.w};
        union { __nv_bfloat16 h[4]; uint2 u; } hu, lu;
        #pragma unroll
        for (int j = 0; j < 4; ++j) {
            float yy = (y[j] - mu) * rs * gs[i * 4 + j] + bs[i * 4 + j];
            __nv_bfloat16 hi = __float2bfloat16(yy);
            hu.h[j] = hi;
            lu.h[j] = __float2bfloat16(yy - __bfloat162float(hi));
        }
        *(uint2*)(ah + i * 4) = hu.u;
        *(uint2*)(al + i * 4) = lu.u;
    }
}

// ---------------------------------------------------------------------------
// Kernel 2: W1 transpose + bf16 hi/lo split. out[n][k] = split(W1[k][n]).
// ---------------------------------------------------------------------------
__global__ __launch_bounds__(256)
void w1_convert_kernel(const float* __restrict__ W1) {
    __shared__ float t[32][33];
    const int tx = threadIdx.x, ty = threadIdx.y;    // 32x8
    const int bn = blockIdx.x * 32, bk = blockIdx.y * 32;
    #pragma unroll
    for (int i = 0; i < 4; ++i)
        t[ty + i * 8][tx] = W1[(size_t)(bk + ty + i * 8) * CC + bn + tx];
    __syncthreads();
    #pragma unroll
    for (int i = 0; i < 4; ++i) {
        const int n = bn + ty + i * 8, k = bk + tx;
        float v = t[tx][ty + i * 8];
        __nv_bfloat16 hi = __float2bfloat16(v);
        g_W1Thi[(size_t)n * CC + k] = hi;
        g_W1Tlo[(size_t)n * CC + k] = __float2bfloat16(v - __bfloat162float(hi));
    }
}

// ---------------------------------------------------------------------------
// Kernel 3: mma.sync bf16 split GEMM  logits += GELU(LN(x)@W1 + b1) @ W2
// CTA tile 128x128, 8 warps (4x2), warp 32x64, K-chunks of 64, double-buffer.
// SW128-style swizzle (rows of 128B): phys = row*128 + ((seg ^ (row&7))<<4)+in16
// ---------------------------------------------------------------------------
#define KC      64
#define NCH     12                 // 768/64
#define TILE_B  16384              // 128 rows x 128 bytes
#define BUFSZ   (4 * TILE_B)       // A_hi | A_lo | B_hi | B_lo
#define OFF_ALO TILE_B
#define OFF_BHI (2 * TILE_B)
#define OFF_BLO (3 * TILE_B)
#define SM_W2   (2 * BUFSZ)        // 131072: W2s 128x8 f32 = 4KB
#define SM_B1   (SM_W2 + 4096)     // b1s 128 f32
#define SM_TOTAL (SM_B1 + 512 + 1024)

__device__ __forceinline__ void load_tile_cp(uint32_t dst, const __nv_bfloat16* src,
                                             int tid) {
    // 128 rows x 64 bf16 (128B), 1024 x 16B cp.async, 4 per thread
    #pragma unroll
    for (int j = 0; j < 4; ++j) {
        const int c = tid + j * 256;
        const int row = c >> 3, seg = c & 7;
        const uint32_t off = (uint32_t)(row * 128) + (uint32_t)((seg ^ (row & 7)) << 4);
        CP_ASYNC16(dst + off, src + (size_t)row * CC + seg * 8);
    }
}

__global__ __launch_bounds__(256, 1)
void gemm_kernel(const float* __restrict__ W2, const float* __restrict__ b1) {
    extern __shared__ __align__(16) char smraw[];
    const uint32_t sbraw = smem_to_u32(smraw);
    const uint32_t sb = (sbraw + 1023u) & ~1023u;
    char* sm = smraw + (sb - sbraw);
    float* W2s = (float*)(sm + SM_W2);
    float* b1s = (float*)(sm + SM_B1);

    const int tid = threadIdx.x;
    const int wid = tid >> 5;
    const int lid = tid & 31;
    const int warp_m = wid & 3;          // 4 along M
    const int warp_n = wid >> 2;         // 2 along N
    const int n0 = blockIdx.x * 128;     // x fastest -> same-row CTAs adjacent
    const int r0 = blockIdx.y * 128;

    for (int i = tid; i < 1024; i += 256) W2s[i] = W2[(size_t)n0 * KK + i];
    if (tid < 128) b1s[tid] = b1[n0 + tid];

    // preload chunk 0
    {
        const uint32_t bb = sb;
        load_tile_cp(bb,            g_Ahi   + (size_t)r0 * CC, tid);
        load_tile_cp(bb + OFF_ALO,  g_Alo   + (size_t)r0 * CC, tid);
        load_tile_cp(bb + OFF_BHI,  g_W1Thi + (size_t)n0 * CC, tid);
        load_tile_cp(bb + OFF_BLO,  g_W1Tlo + (size_t)n0 * CC, tid);
        CP_COMMIT();
    }

    float acc[2][8][4];
    #pragma unroll
    for (int mf = 0; mf < 2; ++mf)
        #pragma unroll
        for (int nf = 0; nf < 8; ++nf)
            #pragma unroll
            for (int r = 0; r < 4; ++r) acc[mf][nf][r] = 0.f;

    // precomputed ldmatrix lane components
    const int a_row = warp_m * 32 + (lid & 15);       // + mf*16
    const int a_seg = lid >> 4;                       // + ks*2
    const int b_mat = lid >> 3;
    const int b_row = warp_n * 64 + ((b_mat >> 1) << 3) + (lid & 7);  // + np*16
    const int b_seg = b_mat & 1;                      // + ks*2

    for (int i = 0; i < NCH; ++i) {
        if (i + 1 < NCH) {
            const uint32_t bb = sb + ((i + 1) & 1) * BUFSZ;
            const int k0 = (i + 1) * KC;
            load_tile_cp(bb,           g_Ahi   + (size_t)r0 * CC + k0, tid);
            load_tile_cp(bb + OFF_ALO, g_Alo   + (size_t)r0 * CC + k0, tid);
            load_tile_cp(bb + OFF_BHI, g_W1Thi + (size_t)n0 * CC + k0, tid);
            load_tile_cp(bb + OFF_BLO, g_W1Tlo + (size_t)n0 * CC + k0, tid);
            CP_COMMIT();
            CP_WAIT(1);
        } else {
            CP_WAIT(0);
        }
        __syncthreads();

        const uint32_t bb = sb + (i & 1) * BUFSZ;
        #pragma unroll
        for (int ks = 0; ks < 4; ++ks) {
            uint32_t ah[2][4], al[2][4];
            #pragma unroll
            for (int mf = 0; mf < 2; ++mf) {
                const int row = a_row + mf * 16;
                const int seg = a_seg + ks * 2;
                const uint32_t off = (uint32_t)(row * 128) +
                                     (uint32_t)(((seg ^ (row & 7)) & 7) << 4);
                ldsm_x4(ah[mf], bb + off);
                ldsm_x4(al[mf], bb + OFF_ALO + off);
            }
            #pragma unroll
            for (int np = 0; np < 4; ++np) {
                uint32_t bh[4], bl[4];
                {
                    const int row = b_row + np * 16;
                    const int seg = b_seg + ks * 2;
                    const uint32_t off = (uint32_t)(row * 128) +
                                         (uint32_t)(((seg ^ (row & 7)) & 7) << 4);
                    ldsm_x4(bh, bb + OFF_BHI + off);
                    ldsm_x4(bl, bb + OFF_BLO + off);
                }
                #pragma unroll
                for (int mf = 0; mf < 2; ++mf) {
                    #pragma unroll
                    for (int h = 0; h < 2; ++h) {
                        float (&d)[4] = acc[mf][np * 2 + h];
                        mma_bf16(d, ah[mf], bh + h * 2);
                        mma_bf16(d, ah[mf], bl + h * 2);
                        mma_bf16(d, al[mf], bh + h * 2);
                    }
                }
            }
        }
        __syncthreads();
    }

    // ---------------- Epilogue: +b1, GELU, fold W2, reduce ----------------
    float* logits_s = (float*)sm;        // reuse buffer smem: 128x8 f32
    for (int i = tid; i < 1024; i += 256) logits_s[i] = 0.f;
    __syncthreads();

    const int qr = lid >> 2, qc = lid & 3;
    #pragma unroll
    for (int mf = 0; mf < 2; ++mf) {
        float lg[2][8];
        #pragma unroll
        for (int h = 0; h < 2; ++h)
            #pragma unroll
            for (int k = 0; k < 8; ++k) lg[h][k] = 0.f;

        #pragma unroll
        for (int nf = 0; nf < 8; ++nf) {
            const int colb = warp_n * 64 + nf * 8 + qc * 2;
            #pragma unroll
            for (int r = 0; r < 4; ++r) {
                const int c = colb + (r & 1);
                const float v = acc[mf][nf][r] + b1s[c];
                const float hh = gelu_exact(v);
                const float* w = &W2s[c * 8];
                float* l = lg[r >> 1];
                #pragma unroll
                for (int k = 0; k < 8; ++k) l[k] = fmaf(hh, w[k], l[k]);
            }
        }
        const int rA = warp_m * 32 + mf * 16 + qr;
        #pragma unroll
        for (int k = 0; k < 8; ++k) {
            atomicAdd(&logits_s[rA * 8 + k],       lg[0][k]);
            atomicAdd(&logits_s[(rA + 8) * 8 + k], lg[1][k]);
        }
    }
    __syncthreads();

    for (int i = tid; i < 1024; i += 256) {
        const int r = i >> 3, k = i & 7;
        atomicAdd(&g_logits[(size_t)(r0 + r) * KK + k], logits_s[i]);
    }
}

// ---------------------------------------------------------------------------
// Kernel 4: softmax over tokens per (b,k). (b2 dropped: constant over n.)
// ---------------------------------------------------------------------------
__global__ __launch_bounds__(256)
void softmax_kernel() {
    __shared__ float red[8];
    __shared__ float bcast;
    const int b  = blockIdx.x >> 3;
    const int kk = blockIdx.x & 7;
    const int tid = threadIdx.x;
    float* base = g_logits + (size_t)b * NN * KK + kk;

    float v[16];
    float mx = -1e30f;
    #pragma unroll
    for (int i = 0; i < 16; ++i) {
        v[i] = base[(size_t)(i * 256 + tid) * KK];
        mx = fmaxf(mx, v[i]);
    }
    #pragma unroll
    for (int o = 16; o; o >>= 1) mx = fmaxf(mx, __shfl_xor_sync(0xffffffffu, mx, o));
    if ((tid & 31) == 0) red[tid >> 5] = mx;
    __syncthreads();
    if (tid < 32) {
        float m = (tid < 8) ? red[tid] : -1e30f;
        #pragma unroll
        for (int o = 4; o; o >>= 1) m = fmaxf(m, __shfl_xor_sync(0xffffffffu, m, o));
        if (tid == 0) bcast = m;
    }
    __syncthreads();
    mx = bcast;

    float s = 0.f;
    #pragma unroll
    for (int i = 0; i < 16; ++i) { v[i] = __expf(v[i] - mx); s += v[i]; }
    #pragma unroll
    for (int o = 16; o; o >>= 1) s += __shfl_xor_sync(0xffffffffu, s, o);
    __syncthreads();
    if ((tid & 31) == 0) red[tid >> 5] = s;
    __syncthreads();
    if (tid < 32) {
        float t = (tid < 8) ? red[tid] : 0.f;
        #pragma unroll
        for (int o = 4; o; o >>= 1) t += __shfl_xor_sync(0xffffffffu, t, o);
        if (tid == 0) bcast = t;
    }
    __syncthreads();
    const float inv = 1.0f / bcast;
    #pragma unroll
    for (int i = 0; i < 16; ++i)
        base[(size_t)(i * 256 + tid) * KK] = v[i] * inv;
}

// ---------------------------------------------------------------------------
// Kernel 5: out[b,k,c] = sum_n attn[b,n,k] * x[b,n,c]
// ---------------------------------------------------------------------------
__global__ __launch_bounds__(256)
void pool_kernel(const float* __restrict__ x, float* __restrict__ out) {
    __shared__ float attn_s[1024][8];
    const int nc = blockIdx.x;
    const int ct = blockIdx.y;
    const int b  = blockIdx.z;
    const int n0 = nc * 1024;

    const float* lp = g_logits + ((size_t)b * NN + n0) * KK;
    for (int i = threadIdx.x; i < 1024 * 8 / 4; i += 256)
        ((float4*)attn_s)[i] = ((const float4*)lp)[i];
    __syncthreads();

    const int c = ct * 256 + threadIdx.x;
    const float* xp = x + ((size_t)b * NN + n0) * CC + c;
    float acc[8];
    #pragma unroll
    for (int kk = 0; kk < 8; ++kk) acc[kk] = 0.f;

    #pragma unroll 4
    for (int n = 0; n < 1024; ++n) {
        const float xv = xp[(size_t)n * CC];
        float4 a0 = *(const float4*)(&attn_s[n][0]);
        float4 a1 = *(const float4*)(&attn_s[n][4]);
        acc[0] = fmaf(a0.x, xv, acc[0]);
        acc[1] = fmaf(a0.y, xv, acc[1]);
        acc[2] = fmaf(a0.z, xv, acc[2]);
        acc[3] = fmaf(a0.w, xv, acc[3]);
        acc[4] = fmaf(a1.x, xv, acc[4]);
        acc[5] = fmaf(a1.y, xv, acc[5]);
        acc[6] = fmaf(a1.z, xv, acc[6]);
        acc[7] = fmaf(a1.w, xv, acc[7]);
    }
    #pragma unroll
    for (int kk = 0; kk < 8; ++kk)
        atomicAdd(&out[((size_t)b * KK + kk) * CC + c], acc[kk]);
}

// ---------------------------------------------------------------------------
extern "C" void kernel_launch(void* const* d_in, const int* in_sizes, int n_in,
                              void* d_out, int out_size) {
    const float* x     = (const float*)d_in[0];
    const float* gamma = (const float*)d_in[1];
    const float* beta  = (const float*)d_in[2];
    const float* W1    = (const float*)d_in[3];
    const float* b1    = (const float*)d_in[4];
    const float* W2    = (const float*)d_in[5];
    // b2 (d_in[6]) unused: constant over tokens -> cancels in softmax
    float* out = (float*)d_out;

    cudaMemsetAsync(out, 0, (size_t)out_size * sizeof(float));
    ln_convert_kernel<<<MM / 8, 256>>>(x, gamma, beta);
    w1_convert_kernel<<<dim3(CC / 32, CC / 32), dim3(32, 8)>>>(W1);
    cudaFuncSetAttribute(gemm_kernel, cudaFuncAttributeMaxDynamicSharedMemorySize, SM_TOTAL);
    gemm_kernel<<<dim3(6, MM / 128), 256, SM_TOTAL>>>(W2, b1);
    softmax_kernel<<<BB * KK, 256>>>();
    pool_kernel<<<dim3(4, 3, 32), 256>>>(x, out);
}

// round 5
// speedup vs baseline: 4.3038x; 1.2225x over previous
#include <cuda_runtime.h>
#include <cuda_bf16.h>
#include <cstdint>
#include <cstddef>

#define BB 32
#define NN 4096
#define CC 768
#define KK 8
#define MM (BB * NN)   // 131072 rows

// Scratch (__device__ globals; allocation-free rule)
__device__ __nv_bfloat16 g_Ahi[(size_t)MM * CC];   // LN(x) hi, bf16
__device__ __nv_bfloat16 g_Alo[(size_t)MM * CC];   // LN(x) lo, bf16
__device__ __nv_bfloat16 g_W1Thi[(size_t)CC * CC]; // W1^T hi ([n][k], k contiguous)
__device__ __nv_bfloat16 g_W1Tlo[(size_t)CC * CC];
__device__ float g_logits[(size_t)MM * KK];

// ---------------------------------------------------------------------------
// PTX helpers (plain-sm_103-legal: mma.sync, ldmatrix, cp.async)
// ---------------------------------------------------------------------------
__device__ __forceinline__ uint32_t smem_to_u32(const void* p) {
    uint32_t a;
    asm("{ .reg .u64 t; cvta.to.shared.u64 t, %1; cvt.u32.u64 %0, t; }"
        : "=r"(a) : "l"(p));
    return a;
}
#define CP_ASYNC16(dst, src) \
    asm volatile("cp.async.cg.shared.global [%0], [%1], 16;" :: "r"(dst), "l"(src))
#define CP_COMMIT() asm volatile("cp.async.commit_group;" ::: "memory")
#define CP_WAIT(n)  asm volatile("cp.async.wait_group %0;" :: "n"(n) : "memory")

__device__ __forceinline__ void ldsm_x4(uint32_t (&r)[4], uint32_t addr) {
    asm volatile("ldmatrix.sync.aligned.m8n8.x4.shared.b16 {%0,%1,%2,%3}, [%4];"
        : "=r"(r[0]), "=r"(r[1]), "=r"(r[2]), "=r"(r[3]) : "r"(addr));
}
__device__ __forceinline__ void mma_bf16(float (&d)[4], const uint32_t (&a)[4],
                                         const uint32_t* b) {
    asm volatile(
        "mma.sync.aligned.m16n8k16.row.col.f32.bf16.bf16.f32 "
        "{%0,%1,%2,%3}, {%4,%5,%6,%7}, {%8,%9}, {%0,%1,%2,%3};"
        : "+f"(d[0]), "+f"(d[1]), "+f"(d[2]), "+f"(d[3])
        : "r"(a[0]), "r"(a[1]), "r"(a[2]), "r"(a[3]), "r"(b[0]), "r"(b[1]));
}

__device__ __forceinline__ float gelu_exact(float v) {
    return 0.5f * v * (1.0f + erff(v * 0.70710678118654752440f));
}

// ---------------------------------------------------------------------------
// Kernel 1: fused LN stats + bf16 hi/lo split. One warp per row. Zeroes logits.
// ---------------------------------------------------------------------------
__global__ __launch_bounds__(256)
void ln_convert_kernel(const float* __restrict__ x,
                       const float* __restrict__ gamma,
                       const float* __restrict__ beta) {
    __shared__ float gs[CC], bs[CC];
    const int tid = threadIdx.x;
    for (int i = tid; i < CC; i += 256) { gs[i] = gamma[i]; bs[i] = beta[i]; }
    if (blockIdx.x < (MM * KK) / 256)
        g_logits[(size_t)blockIdx.x * 256 + tid] = 0.f;
    __syncthreads();

    const int row  = blockIdx.x * 8 + (tid >> 5);
    const int lane = tid & 31;
    const float4* r = (const float4*)(x + (size_t)row * CC);
    float s = 0.f, ss = 0.f;
    #pragma unroll
    for (int i = lane; i < CC / 4; i += 32) {
        float4 v = r[i];
        s  += v.x + v.y + v.z + v.w;
        ss += v.x * v.x + v.y * v.y + v.z * v.z + v.w * v.w;
    }
    #pragma unroll
    for (int o = 16; o; o >>= 1) {
        s  += __shfl_xor_sync(0xffffffffu, s,  o);
        ss += __shfl_xor_sync(0xffffffffu, ss, o);
    }
    const float mu = s * (1.0f / CC);
    const float rs = rsqrtf(ss * (1.0f / CC) - mu * mu + 1e-5f);

    __nv_bfloat16* ah = g_Ahi + (size_t)row * CC;
    __nv_bfloat16* al = g_Alo + (size_t)row * CC;
    #pragma unroll
    for (int i = lane; i < CC / 4; i += 32) {
        float4 v = r[i];
        float y[4] = {v.x, v.y, v.z, v.w};
        union { __nv_bfloat16 h[4]; uint2 u; } hu, lu;
        #pragma unroll
        for (int j = 0; j < 4; ++j) {
            float yy = (y[j] - mu) * rs * gs[i * 4 + j] + bs[i * 4 + j];
            __nv_bfloat16 hi = __float2bfloat16(yy);
            hu.h[j] = hi;
            lu.h[j] = __float2bfloat16(yy - __bfloat162float(hi));
        }
        *(uint2*)(ah + i * 4) = hu.u;
        *(uint2*)(al + i * 4) = lu.u;
    }
}

// ---------------------------------------------------------------------------
// Kernel 2: W1 transpose + bf16 hi/lo split. out[n][k] = split(W1[k][n]).
// ---------------------------------------------------------------------------
__global__ __launch_bounds__(256)
void w1_convert_kernel(const float* __restrict__ W1) {
    __shared__ float t[32][33];
    const int tx = threadIdx.x, ty = threadIdx.y;    // 32x8
    const int bn = blockIdx.x * 32, bk = blockIdx.y * 32;
    #pragma unroll
    for (int i = 0; i < 4; ++i)
        t[ty + i * 8][tx] = W1[(size_t)(bk + ty + i * 8) * CC + bn + tx];
    __syncthreads();
    #pragma unroll
    for (int i = 0; i < 4; ++i) {
        const int n = bn + ty + i * 8, k = bk + tx;
        float v = t[tx][ty + i * 8];
        __nv_bfloat16 hi = __float2bfloat16(v);
        g_W1Thi[(size_t)n * CC + k] = hi;
        g_W1Tlo[(size_t)n * CC + k] = __float2bfloat16(v - __bfloat162float(hi));
    }
}

// ---------------------------------------------------------------------------
// Kernel 3: mma.sync bf16 split GEMM  logits += GELU(LN(x)@W1 + b1) @ W2
// CTA tile 128x128, 8 warps (4x2), warp 32x64, KC=32, 3-stage pipeline,
// 2 CTAs/SM. Rows of 64B; swizzle: seg ^= (row>>1)&3.
// ---------------------------------------------------------------------------
#define KC      32
#define NCH     24                 // 768/32
#define TILE_B  8192               // 128 rows x 64 bytes
#define BUFSZ   (4 * TILE_B)       // A_hi | A_lo | B_hi | B_lo = 32KB
#define OFF_ALO TILE_B
#define OFF_BHI (2 * TILE_B)
#define OFF_BLO (3 * TILE_B)
#define NSTAGE  3
#define SM_W2   (NSTAGE * BUFSZ)   // 98304
#define SM_B1   (SM_W2 + 4096)
#define SM_TOTAL (SM_B1 + 512 + 1024)

__device__ __forceinline__ uint32_t swz(int row, int seg) {
    return (uint32_t)(row * 64) + (uint32_t)(((seg ^ ((row >> 1) & 3)) & 3) << 4);
}

__device__ __forceinline__ void load_tile_cp(uint32_t dst, const __nv_bfloat16* src,
                                             int tid) {
    // 128 rows x 32 bf16 (64B rows) = 512 x 16B, 2 per thread
    #pragma unroll
    for (int j = 0; j < 2; ++j) {
        const int c = tid + j * 256;
        const int row = c >> 2, seg = c & 3;
        CP_ASYNC16(dst + swz(row, seg), src + (size_t)row * CC + seg * 8);
    }
}

__global__ __launch_bounds__(256, 2)
void gemm_kernel(const float* __restrict__ W2, const float* __restrict__ b1) {
    extern __shared__ __align__(16) char smraw[];
    const uint32_t sbraw = smem_to_u32(smraw);
    const uint32_t sb = (sbraw + 1023u) & ~1023u;
    char* sm = smraw + (sb - sbraw);
    float* W2s = (float*)(sm + SM_W2);
    float* b1s = (float*)(sm + SM_B1);

    const int tid = threadIdx.x;
    const int wid = tid >> 5;
    const int lid = tid & 31;
    const int warp_m = wid & 3;          // 4 along M
    const int warp_n = wid >> 2;         // 2 along N
    const int n0 = blockIdx.x * 128;
    const int r0 = blockIdx.y * 128;

    const __nv_bfloat16* pAhi = g_Ahi   + (size_t)r0 * CC;
    const __nv_bfloat16* pAlo = g_Alo   + (size_t)r0 * CC;
    const __nv_bfloat16* pBhi = g_W1Thi + (size_t)n0 * CC;
    const __nv_bfloat16* pBlo = g_W1Tlo + (size_t)n0 * CC;

    for (int i = tid; i < 1024; i += 256) W2s[i] = W2[(size_t)n0 * KK + i];
    if (tid < 128) b1s[tid] = b1[n0 + tid];

    // prologue: stages 0, 1
    #pragma unroll
    for (int st = 0; st < 2; ++st) {
        const uint32_t bb = sb + st * BUFSZ;
        const int k0 = st * KC;
        load_tile_cp(bb,           pAhi + k0, tid);
        load_tile_cp(bb + OFF_ALO, pAlo + k0, tid);
        load_tile_cp(bb + OFF_BHI, pBhi + k0, tid);
        load_tile_cp(bb + OFF_BLO, pBlo + k0, tid);
        CP_COMMIT();
    }

    float acc[2][8][4];
    #pragma unroll
    for (int mf = 0; mf < 2; ++mf)
        #pragma unroll
        for (int nf = 0; nf < 8; ++nf)
            #pragma unroll
            for (int r = 0; r < 4; ++r) acc[mf][nf][r] = 0.f;

    const int a_row = warp_m * 32 + (lid & 15);                       // + mf*16
    const int a_seg = lid >> 4;                                       // + ks*2
    const int b_mat = lid >> 3;
    const int b_row = warp_n * 64 + ((b_mat >> 1) << 3) + (lid & 7);  // + np*16
    const int b_seg = b_mat & 1;                                      // + ks*2

    int stage = 0;
    for (int i = 0; i < NCH; ++i) {
        if (i < NCH - 1) CP_WAIT(1); else CP_WAIT(0);
        __syncthreads();

        // prefetch stage i+2 (overwrites buffer of stage i-1; safe after sync)
        if (i + 2 < NCH) {
            int st2 = stage + 2; if (st2 >= NSTAGE) st2 -= NSTAGE;
            const uint32_t bb = sb + st2 * BUFSZ;
            const int k0 = (i + 2) * KC;
            load_tile_cp(bb,           pAhi + k0, tid);
            load_tile_cp(bb + OFF_ALO, pAlo + k0, tid);
            load_tile_cp(bb + OFF_BHI, pBhi + k0, tid);
            load_tile_cp(bb + OFF_BLO, pBlo + k0, tid);
            CP_COMMIT();
        }

        const uint32_t bb = sb + stage * BUFSZ;
        #pragma unroll
        for (int ks = 0; ks < 2; ++ks) {
            uint32_t ah[2][4], al[2][4];
            #pragma unroll
            for (int mf = 0; mf < 2; ++mf) {
                const uint32_t off = swz(a_row + mf * 16, a_seg + ks * 2);
                ldsm_x4(ah[mf], bb + off);
                ldsm_x4(al[mf], bb + OFF_ALO + off);
            }
            #pragma unroll
            for (int np = 0; np < 4; ++np) {
                uint32_t bh[4], bl[4];
                {
                    const uint32_t off = swz(b_row + np * 16, b_seg + ks * 2);
                    ldsm_x4(bh, bb + OFF_BHI + off);
                    ldsm_x4(bl, bb + OFF_BLO + off);
                }
                #pragma unroll
                for (int mf = 0; mf < 2; ++mf) {
                    #pragma unroll
                    for (int h = 0; h < 2; ++h) {
                        float (&d)[4] = acc[mf][np * 2 + h];
                        mma_bf16(d, ah[mf], bh + h * 2);
                        mma_bf16(d, ah[mf], bl + h * 2);
                        mma_bf16(d, al[mf], bh + h * 2);
                    }
                }
            }
        }
        ++stage; if (stage == NSTAGE) stage = 0;
    }
    __syncthreads();

    // ---------------- Epilogue: +b1, GELU, fold W2, reduce ----------------
    float* logits_s = (float*)sm;        // reuse pipeline smem: 128x8 f32
    for (int i = tid; i < 1024; i += 256) logits_s[i] = 0.f;
    __syncthreads();

    const int qr = lid >> 2, qc = lid & 3;
    #pragma unroll
    for (int mf = 0; mf < 2; ++mf) {
        float lg[2][8];
        #pragma unroll
        for (int h = 0; h < 2; ++h)
            #pragma unroll
            for (int k = 0; k < 8; ++k) lg[h][k] = 0.f;

        #pragma unroll
        for (int nf = 0; nf < 8; ++nf) {
            const int colb = warp_n * 64 + nf * 8 + qc * 2;
            #pragma unroll
            for (int r = 0; r < 4; ++r) {
                const int c = colb + (r & 1);
                const float v = acc[mf][nf][r] + b1s[c];
                const float hh = gelu_exact(v);
                const float* w = &W2s[c * 8];
                float* l = lg[r >> 1];
                #pragma unroll
                for (int k = 0; k < 8; ++k) l[k] = fmaf(hh, w[k], l[k]);
            }
        }
        const int rA = warp_m * 32 + mf * 16 + qr;
        #pragma unroll
        for (int k = 0; k < 8; ++k) {
            atomicAdd(&logits_s[rA * 8 + k],       lg[0][k]);
            atomicAdd(&logits_s[(rA + 8) * 8 + k], lg[1][k]);
        }
    }
    __syncthreads();

    for (int i = tid; i < 1024; i += 256) {
        const int r = i >> 3, k = i & 7;
        atomicAdd(&g_logits[(size_t)(r0 + r) * KK + k], logits_s[i]);
    }
}

// ---------------------------------------------------------------------------
// Kernel 4: softmax over tokens per (b,k). (b2 dropped: constant over n.)
// ---------------------------------------------------------------------------
__global__ __launch_bounds__(256)
void softmax_kernel() {
    __shared__ float red[8];
    __shared__ float bcast;
    const int b  = blockIdx.x >> 3;
    const int kk = blockIdx.x & 7;
    const int tid = threadIdx.x;
    float* base = g_logits + (size_t)b * NN * KK + kk;

    float v[16];
    float mx = -1e30f;
    #pragma unroll
    for (int i = 0; i < 16; ++i) {
        v[i] = base[(size_t)(i * 256 + tid) * KK];
        mx = fmaxf(mx, v[i]);
    }
    #pragma unroll
    for (int o = 16; o; o >>= 1) mx = fmaxf(mx, __shfl_xor_sync(0xffffffffu, mx, o));
    if ((tid & 31) == 0) red[tid >> 5] = mx;
    __syncthreads();
    if (tid < 32) {
        float m = (tid < 8) ? red[tid] : -1e30f;
        #pragma unroll
        for (int o = 4; o; o >>= 1) m = fmaxf(m, __shfl_xor_sync(0xffffffffu, m, o));
        if (tid == 0) bcast = m;
    }
    __syncthreads();
    mx = bcast;

    float s = 0.f;
    #pragma unroll
    for (int i = 0; i < 16; ++i) { v[i] = __expf(v[i] - mx); s += v[i]; }
    #pragma unroll
    for (int o = 16; o; o >>= 1) s += __shfl_xor_sync(0xffffffffu, s, o);
    __syncthreads();
    if ((tid & 31) == 0) red[tid >> 5] = s;
    __syncthreads();
    if (tid < 32) {
        float t = (tid < 8) ? red[tid] : 0.f;
        #pragma unroll
        for (int o = 4; o; o >>= 1) t += __shfl_xor_sync(0xffffffffu, t, o);
        if (tid == 0) bcast = t;
    }
    __syncthreads();
    const float inv = 1.0f / bcast;
    #pragma unroll
    for (int i = 0; i < 16; ++i)
        base[(size_t)(i * 256 + tid) * KK] = v[i] * inv;
}

// ---------------------------------------------------------------------------
// Kernel 5: out[b,k,c] = sum_n attn[b,n,k] * x[b,n,c]
// ---------------------------------------------------------------------------
__global__ __launch_bounds__(256)
void pool_kernel(const float* __restrict__ x, float* __restrict__ out) {
    __shared__ float attn_s[1024][8];
    const int nc = blockIdx.x;
    const int ct = blockIdx.y;
    const int b  = blockIdx.z;
    const int n0 = nc * 1024;

    const float* lp = g_logits + ((size_t)b * NN + n0) * KK;
    for (int i = threadIdx.x; i < 1024 * 8 / 4; i += 256)
        ((float4*)attn_s)[i] = ((const float4*)lp)[i];
    __syncthreads();

    const int c = ct * 256 + threadIdx.x;
    const float* xp = x + ((size_t)b * NN + n0) * CC + c;
    float acc[8];
    #pragma unroll
    for (int kk = 0; kk < 8; ++kk) acc[kk] = 0.f;

    #pragma unroll 4
    for (int n = 0; n < 1024; ++n) {
        const float xv = xp[(size_t)n * CC];
        float4 a0 = *(const float4*)(&attn_s[n][0]);
        float4 a1 = *(const float4*)(&attn_s[n][4]);
        acc[0] = fmaf(a0.x, xv, acc[0]);
        acc[1] = fmaf(a0.y, xv, acc[1]);
        acc[2] = fmaf(a0.z, xv, acc[2]);
        acc[3] = fmaf(a0.w, xv, acc[3]);
        acc[4] = fmaf(a1.x, xv, acc[4]);
        acc[5] = fmaf(a1.y, xv, acc[5]);
        acc[6] = fmaf(a1.z, xv, acc[6]);
        acc[7] = fmaf(a1.w, xv, acc[7]);
    }
    #pragma unroll
    for (int kk = 0; kk < 8; ++kk)
        atomicAdd(&out[((size_t)b * KK + kk) * CC + c], acc[kk]);
}

// ---------------------------------------------------------------------------
extern "C" void kernel_launch(void* const* d_in, const int* in_sizes, int n_in,
                              void* d_out, int out_size) {
    const float* x     = (const float*)d_in[0];
    const float* gamma = (const float*)d_in[1];
    const float* beta  = (const float*)d_in[2];
    const float* W1    = (const float*)d_in[3];
    const float* b1    = (const float*)d_in[4];
    const float* W2    = (const float*)d_in[5];
    // b2 (d_in[6]) unused: constant over tokens -> cancels in softmax
    float* out = (float*)d_out;

    cudaMemsetAsync(out, 0, (size_t)out_size * sizeof(float));
    ln_convert_kernel<<<MM / 8, 256>>>(x, gamma, beta);
    w1_convert_kernel<<<dim3(CC / 32, CC / 32), dim3(32, 8)>>>(W1);
    cudaFuncSetAttribute(gemm_kernel, cudaFuncAttributeMaxDynamicSharedMemorySize, SM_TOTAL);
    gemm_kernel<<<dim3(6, MM / 128), 256, SM_TOTAL>>>(W2, b1);
    softmax_kernel<<<BB * KK, 256>>>();
    pool_kernel<<<dim3(4, 3, 32), 256>>>(x, out);
}

// round 6
// speedup vs baseline: 8.1619x; 1.8964x over previous
#include <cuda_runtime.h>
#include <cuda_fp16.h>
#include <cstdint>
#include <cstddef>

#define BB 32
#define NN 4096
#define CC 768
#define KK 8
#define MM (BB * NN)   // 131072 rows

// Scratch (__device__ globals; allocation-free rule)
__device__ __half g_A[(size_t)MM * CC];     // LN(x), fp16
__device__ __half g_W1T[(size_t)CC * CC];   // W1^T ([n][k], k contiguous), fp16
__device__ float g_logits[(size_t)MM * KK];

// ---------------------------------------------------------------------------
// PTX helpers (plain-sm_103-legal: mma.sync, ldmatrix, cp.async)
// ---------------------------------------------------------------------------
__device__ __forceinline__ uint32_t smem_to_u32(const void* p) {
    uint32_t a;
    asm("{ .reg .u64 t; cvta.to.shared.u64 t, %1; cvt.u32.u64 %0, t; }"
        : "=r"(a) : "l"(p));
    return a;
}
#define CP_ASYNC16(dst, src) \
    asm volatile("cp.async.cg.shared.global [%0], [%1], 16;" :: "r"(dst), "l"(src))
#define CP_COMMIT() asm volatile("cp.async.commit_group;" ::: "memory")
#define CP_WAIT(n)  asm volatile("cp.async.wait_group %0;" :: "n"(n) : "memory")

__device__ __forceinline__ void ldsm_x4(uint32_t (&r)[4], uint32_t addr) {
    asm volatile("ldmatrix.sync.aligned.m8n8.x4.shared.b16 {%0,%1,%2,%3}, [%4];"
        : "=r"(r[0]), "=r"(r[1]), "=r"(r[2]), "=r"(r[3]) : "r"(addr));
}
__device__ __forceinline__ void mma_f16(float (&d)[4], const uint32_t (&a)[4],
                                        const uint32_t* b) {
    asm volatile(
        "mma.sync.aligned.m16n8k16.row.col.f32.f16.f16.f32 "
        "{%0,%1,%2,%3}, {%4,%5,%6,%7}, {%8,%9}, {%0,%1,%2,%3};"
        : "+f"(d[0]), "+f"(d[1]), "+f"(d[2]), "+f"(d[3])
        : "r"(a[0]), "r"(a[1]), "r"(a[2]), "r"(a[3]), "r"(b[0]), "r"(b[1]));
}

__device__ __forceinline__ float gelu_exact(float v) {
    return 0.5f * v * (1.0f + erff(v * 0.70710678118654752440f));
}

// ---------------------------------------------------------------------------
// Kernel 1: fused LN stats + fp16 convert. One warp per row. Zeroes logits.
// ---------------------------------------------------------------------------
__global__ __launch_bounds__(256)
void ln_convert_kernel(const float* __restrict__ x,
                       const float* __restrict__ gamma,
                       const float* __restrict__ beta) {
    __shared__ float gs[CC], bs[CC];
    const int tid = threadIdx.x;
    for (int i = tid; i < CC; i += 256) { gs[i] = gamma[i]; bs[i] = beta[i]; }
    if (blockIdx.x < (MM * KK) / 256)
        g_logits[(size_t)blockIdx.x * 256 + tid] = 0.f;
    __syncthreads();

    const int row  = blockIdx.x * 8 + (tid >> 5);
    const int lane = tid & 31;
    const float4* r = (const float4*)(x + (size_t)row * CC);
    float s = 0.f, ss = 0.f;
    #pragma unroll
    for (int i = lane; i < CC / 4; i += 32) {
        float4 v = r[i];
        s  += v.x + v.y + v.z + v.w;
        ss += v.x * v.x + v.y * v.y + v.z * v.z + v.w * v.w;
    }
    #pragma unroll
    for (int o = 16; o; o >>= 1) {
        s  += __shfl_xor_sync(0xffffffffu, s,  o);
        ss += __shfl_xor_sync(0xffffffffu, ss, o);
    }
    const float mu = s * (1.0f / CC);
    const float rs = rsqrtf(ss * (1.0f / CC) - mu * mu + 1e-5f);

    __half* ap = g_A + (size_t)row * CC;
    #pragma unroll
    for (int i = lane; i < CC / 4; i += 32) {
        float4 v = r[i];
        float y[4] = {v.x, v.y, v.z, v.w};
        union { __half h[4]; uint2 u; } hu;
        #pragma unroll
        for (int j = 0; j < 4; ++j)
            hu.h[j] = __float2half((y[j] - mu) * rs * gs[i * 4 + j] + bs[i * 4 + j]);
        *(uint2*)(ap + i * 4) = hu.u;
    }
}

// ---------------------------------------------------------------------------
// Kernel 2: W1 transpose + fp16 convert. out[n][k] = fp16(W1[k][n]).
// ---------------------------------------------------------------------------
__global__ __launch_bounds__(256)
void w1_convert_kernel(const float* __restrict__ W1) {
    __shared__ float t[32][33];
    const int tx = threadIdx.x, ty = threadIdx.y;    // 32x8
    const int bn = blockIdx.x * 32, bk = blockIdx.y * 32;
    #pragma unroll
    for (int i = 0; i < 4; ++i)
        t[ty + i * 8][tx] = W1[(size_t)(bk + ty + i * 8) * CC + bn + tx];
    __syncthreads();
    #pragma unroll
    for (int i = 0; i < 4; ++i) {
        const int n = bn + ty + i * 8, k = bk + tx;
        g_W1T[(size_t)n * CC + k] = __float2half(t[tx][ty + i * 8]);
    }
}

// ---------------------------------------------------------------------------
// Kernel 3: fp16 mma.sync GEMM  logits += GELU(LN(x)@W1 + b1) @ W2
// CTA tile 128x128, 8 warps (4x2), warp 32x64, KC=64, 3-stage pipeline,
// 2 CTAs/SM. Rows of 128B; swizzle: seg ^= row&7.
// ---------------------------------------------------------------------------
#define KC      64
#define NCH     12                 // 768/64
#define TILE_B  16384              // 128 rows x 128 bytes
#define BUFSZ   (2 * TILE_B)       // A | B = 32KB
#define OFF_B   TILE_B
#define NSTAGE  3
#define SM_W2   (NSTAGE * BUFSZ)   // 98304
#define SM_B1   (SM_W2 + 4096)
#define SM_TOTAL (SM_B1 + 512 + 1024)

__device__ __forceinline__ uint32_t swz(int row, int seg) {
    return (uint32_t)(row * 128) + (uint32_t)(((seg ^ (row & 7)) & 7) << 4);
}

__device__ __forceinline__ void load_tile_cp(uint32_t dst, const __half* src,
                                             int tid) {
    // 128 rows x 64 fp16 (128B rows) = 1024 x 16B, 4 per thread
    #pragma unroll
    for (int j = 0; j < 4; ++j) {
        const int c = tid + j * 256;
        const int row = c >> 3, seg = c & 7;
        CP_ASYNC16(dst + swz(row, seg), src + (size_t)row * CC + seg * 8);
    }
}

__global__ __launch_bounds__(256, 2)
void gemm_kernel(const float* __restrict__ W2, const float* __restrict__ b1) {
    extern __shared__ __align__(16) char smraw[];
    const uint32_t sbraw = smem_to_u32(smraw);
    const uint32_t sb = (sbraw + 1023u) & ~1023u;
    char* sm = smraw + (sb - sbraw);
    float* W2s = (float*)(sm + SM_W2);
    float* b1s = (float*)(sm + SM_B1);

    const int tid = threadIdx.x;
    const int wid = tid >> 5;
    const int lid = tid & 31;
    const int warp_m = wid & 3;          // 4 along M
    const int warp_n = wid >> 2;         // 2 along N
    const int n0 = blockIdx.x * 128;
    const int r0 = blockIdx.y * 128;

    const __half* pA = g_A   + (size_t)r0 * CC;
    const __half* pB = g_W1T + (size_t)n0 * CC;

    for (int i = tid; i < 1024; i += 256) W2s[i] = W2[(size_t)n0 * KK + i];
    if (tid < 128) b1s[tid] = b1[n0 + tid];

    // prologue: stages 0, 1
    #pragma unroll
    for (int st = 0; st < 2; ++st) {
        const uint32_t bb = sb + st * BUFSZ;
        const int k0 = st * KC;
        load_tile_cp(bb,         pA + k0, tid);
        load_tile_cp(bb + OFF_B, pB + k0, tid);
        CP_COMMIT();
    }

    float acc[2][8][4];
    #pragma unroll
    for (int mf = 0; mf < 2; ++mf)
        #pragma unroll
        for (int nf = 0; nf < 8; ++nf)
            #pragma unroll
            for (int r = 0; r < 4; ++r) acc[mf][nf][r] = 0.f;

    const int a_row = warp_m * 32 + (lid & 15);                       // + mf*16
    const int a_seg = lid >> 4;                                       // + ks*2
    const int b_mat = lid >> 3;
    const int b_row = warp_n * 64 + ((b_mat >> 1) << 3) + (lid & 7);  // + np*16
    const int b_seg = b_mat & 1;                                      // + ks*2

    int stage = 0;
    for (int i = 0; i < NCH; ++i) {
        if (i < NCH - 1) CP_WAIT(1); else CP_WAIT(0);
        __syncthreads();

        // prefetch stage i+2 (overwrites buffer of stage i-1; safe after sync)
        if (i + 2 < NCH) {
            int st2 = stage + 2; if (st2 >= NSTAGE) st2 -= NSTAGE;
            const uint32_t bb = sb + st2 * BUFSZ;
            const int k0 = (i + 2) * KC;
            load_tile_cp(bb,         pA + k0, tid);
            load_tile_cp(bb + OFF_B, pB + k0, tid);
            CP_COMMIT();
        }

        const uint32_t bb = sb + stage * BUFSZ;
        #pragma unroll
        for (int ks = 0; ks < 4; ++ks) {
            uint32_t af[2][4];
            #pragma unroll
            for (int mf = 0; mf < 2; ++mf)
                ldsm_x4(af[mf], bb + swz(a_row + mf * 16, a_seg + ks * 2));
            #pragma unroll
            for (int np = 0; np < 4; ++np) {
                uint32_t bf[4];
                ldsm_x4(bf, bb + OFF_B + swz(b_row + np * 16, b_seg + ks * 2));
                #pragma unroll
                for (int mf = 0; mf < 2; ++mf) {
                    mma_f16(acc[mf][np * 2 + 0], af[mf], bf + 0);
                    mma_f16(acc[mf][np * 2 + 1], af[mf], bf + 2);
                }
            }
        }
        ++stage; if (stage == NSTAGE) stage = 0;
    }
    __syncthreads();

    // ---------------- Epilogue: +b1, GELU, fold W2, reduce ----------------
    float* logits_s = (float*)sm;        // reuse pipeline smem: 128x8 f32
    for (int i = tid; i < 1024; i += 256) logits_s[i] = 0.f;
    __syncthreads();

    const int qr = lid >> 2, qc = lid & 3;
    #pragma unroll
    for (int mf = 0; mf < 2; ++mf) {
        float lg[2][8];
        #pragma unroll
        for (int h = 0; h < 2; ++h)
            #pragma unroll
            for (int k = 0; k < 8; ++k) lg[h][k] = 0.f;

        #pragma unroll
        for (int nf = 0; nf < 8; ++nf) {
            const int colb = warp_n * 64 + nf * 8 + qc * 2;
            #pragma unroll
            for (int r = 0; r < 4; ++r) {
                const int c = colb + (r & 1);
                const float v = acc[mf][nf][r] + b1s[c];
                const float hh = gelu_exact(v);
                const float* w = &W2s[c * 8];
                float* l = lg[r >> 1];
                #pragma unroll
                for (int k = 0; k < 8; ++k) l[k] = fmaf(hh, w[k], l[k]);
            }
        }
        const int rA = warp_m * 32 + mf * 16 + qr;
        #pragma unroll
        for (int k = 0; k < 8; ++k) {
            atomicAdd(&logits_s[rA * 8 + k],       lg[0][k]);
            atomicAdd(&logits_s[(rA + 8) * 8 + k], lg[1][k]);
        }
    }
    __syncthreads();

    for (int i = tid; i < 1024; i += 256) {
        const int r = i >> 3, k = i & 7;
        atomicAdd(&g_logits[(size_t)(r0 + r) * KK + k], logits_s[i]);
    }
}

// ---------------------------------------------------------------------------
// Kernel 4: softmax over tokens per (b,k). (b2 dropped: constant over n.)
// ---------------------------------------------------------------------------
__global__ __launch_bounds__(256)
void softmax_kernel() {
    __shared__ float red[8];
    __shared__ float bcast;
    const int b  = blockIdx.x >> 3;
    const int kk = blockIdx.x & 7;
    const int tid = threadIdx.x;
    float* base = g_logits + (size_t)b * NN * KK + kk;

    float v[16];
    float mx = -1e30f;
    #pragma unroll
    for (int i = 0; i < 16; ++i) {
        v[i] = base[(size_t)(i * 256 + tid) * KK];
        mx = fmaxf(mx, v[i]);
    }
    #pragma unroll
    for (int o = 16; o; o >>= 1) mx = fmaxf(mx, __shfl_xor_sync(0xffffffffu, mx, o));
    if ((tid & 31) == 0) red[tid >> 5] = mx;
    __syncthreads();
    if (tid < 32) {
        float m = (tid < 8) ? red[tid] : -1e30f;
        #pragma unroll
        for (int o = 4; o; o >>= 1) m = fmaxf(m, __shfl_xor_sync(0xffffffffu, m, o));
        if (tid == 0) bcast = m;
    }
    __syncthreads();
    mx = bcast;

    float s = 0.f;
    #pragma unroll
    for (int i = 0; i < 16; ++i) { v[i] = __expf(v[i] - mx); s += v[i]; }
    #pragma unroll
    for (int o = 16; o; o >>= 1) s += __shfl_xor_sync(0xffffffffu, s, o);
    __syncthreads();
    if ((tid & 31) == 0) red[tid >> 5] = s;
    __syncthreads();
    if (tid < 32) {
        float t = (tid < 8) ? red[tid] : 0.f;
        #pragma unroll
        for (int o = 4; o; o >>= 1) t += __shfl_xor_sync(0xffffffffu, t, o);
        if (tid == 0) bcast = t;
    }
    __syncthreads();
    const float inv = 1.0f / bcast;
    #pragma unroll
    for (int i = 0; i < 16; ++i)
        base[(size_t)(i * 256 + tid) * KK] = v[i] * inv;
}

// ---------------------------------------------------------------------------
// Kernel 5: out[b,k,c] = sum_n attn[b,n,k] * x[b,n,c]
// ---------------------------------------------------------------------------
__global__ __launch_bounds__(256)
void pool_kernel(const float* __restrict__ x, float* __restrict__ out) {
    __shared__ float attn_s[512][8];     // 16 KB
    const int nc = blockIdx.x;           // 0..7
    const int ct = blockIdx.y;           // 0..2
    const int b  = blockIdx.z;           // 0..31
    const int n0 = nc * 512;

    const float* lp = g_logits + ((size_t)b * NN + n0) * KK;
    for (int i = threadIdx.x; i < 512 * 8 / 4; i += 256)
        ((float4*)attn_s)[i] = ((const float4*)lp)[i];
    __syncthreads();

    const int c = ct * 256 + threadIdx.x;
    const float* xp = x + ((size_t)b * NN + n0) * CC + c;
    float acc[8];
    #pragma unroll
    for (int kk = 0; kk < 8; ++kk) acc[kk] = 0.f;

    #pragma unroll 4
    for (int n = 0; n < 512; ++n) {
        const float xv = xp[(size_t)n * CC];
        float4 a0 = *(const float4*)(&attn_s[n][0]);
        float4 a1 = *(const float4*)(&attn_s[n][4]);
        acc[0] = fmaf(a0.x, xv, acc[0]);
        acc[1] = fmaf(a0.y, xv, acc[1]);
        acc[2] = fmaf(a0.z, xv, acc[2]);
        acc[3] = fmaf(a0.w, xv, acc[3]);
        acc[4] = fmaf(a1.x, xv, acc[4]);
        acc[5] = fmaf(a1.y, xv, acc[5]);
        acc[6] = fmaf(a1.z, xv, acc[6]);
        acc[7] = fmaf(a1.w, xv, acc[7]);
    }
    #pragma unroll
    for (int kk = 0; kk < 8; ++kk)
        atomicAdd(&out[((size_t)b * KK + kk) * CC + c], acc[kk]);
}

// ---------------------------------------------------------------------------
extern "C" void kernel_launch(void* const* d_in, const int* in_sizes, int n_in,
                              void* d_out, int out_size) {
    const float* x     = (const float*)d_in[0];
    const float* gamma = (const float*)d_in[1];
    const float* beta  = (const float*)d_in[2];
    const float* W1    = (const float*)d_in[3];
    const float* b1    = (const float*)d_in[4];
    const float* W2    = (const float*)d_in[5];
    // b2 (d_in[6]) unused: constant over tokens -> cancels in softmax
    float* out = (float*)d_out;

    cudaMemsetAsync(out, 0, (size_t)out_size * sizeof(float));
    ln_convert_kernel<<<MM / 8, 256>>>(x, gamma, beta);
    w1_convert_kernel<<<dim3(CC / 32, CC / 32), dim3(32, 8)>>>(W1);
    cudaFuncSetAttribute(gemm_kernel, cudaFuncAttributeMaxDynamicSharedMemorySize, SM_TOTAL);
    gemm_kernel<<<dim3(6, MM / 128), 256, SM_TOTAL>>>(W2, b1);
    softmax_kernel<<<BB * KK, 256>>>();
    pool_kernel<<<dim3(8, 3, 32), 256>>>(x, out);
}

// round 7
// speedup vs baseline: 8.3574x; 1.0240x over previous
#include <cuda_runtime.h>
#include <cuda_fp16.h>
#include <cstdint>
#include <cstddef>

#define BB 32
#define NN 4096
#define CC 768
#define KK 8
#define MM (BB * NN)   // 131072 rows

// Scratch (__device__ globals; allocation-free rule)
__device__ __half g_A[(size_t)MM * CC];     // LN(x), fp16
__device__ __half g_W1T[(size_t)CC * CC];   // W1^T ([n][k], k contiguous), fp16
__device__ float g_logits[(size_t)MM * KK];
__device__ float g_mx[BB * KK];             // softmax row max per (b,k)
__device__ float g_inv[BB * KK];            // 1/sum per (b,k)

// ---------------------------------------------------------------------------
// PTX helpers (plain-sm_103-legal: mma.sync, ldmatrix, cp.async)
// ---------------------------------------------------------------------------
__device__ __forceinline__ uint32_t smem_to_u32(const void* p) {
    uint32_t a;
    asm("{ .reg .u64 t; cvta.to.shared.u64 t, %1; cvt.u32.u64 %0, t; }"
        : "=r"(a) : "l"(p));
    return a;
}
#define CP_ASYNC16(dst, src) \
    asm volatile("cp.async.cg.shared.global [%0], [%1], 16;" :: "r"(dst), "l"(src))
#define CP_COMMIT() asm volatile("cp.async.commit_group;" ::: "memory")
#define CP_WAIT(n)  asm volatile("cp.async.wait_group %0;" :: "n"(n) : "memory")

__device__ __forceinline__ void ldsm_x4(uint32_t (&r)[4], uint32_t addr) {
    asm volatile("ldmatrix.sync.aligned.m8n8.x4.shared.b16 {%0,%1,%2,%3}, [%4];"
        : "=r"(r[0]), "=r"(r[1]), "=r"(r[2]), "=r"(r[3]) : "r"(addr));
}
__device__ __forceinline__ void mma_f16(float (&d)[4], const uint32_t (&a)[4],
                                        const uint32_t* b) {
    asm volatile(
        "mma.sync.aligned.m16n8k16.row.col.f32.f16.f16.f32 "
        "{%0,%1,%2,%3}, {%4,%5,%6,%7}, {%8,%9}, {%0,%1,%2,%3};"
        : "+f"(d[0]), "+f"(d[1]), "+f"(d[2]), "+f"(d[3])
        : "r"(a[0]), "r"(a[1]), "r"(a[2]), "r"(a[3]), "r"(b[0]), "r"(b[1]));
}

__device__ __forceinline__ float gelu_exact(float v) {
    return 0.5f * v * (1.0f + erff(v * 0.70710678118654752440f));
}

// ---------------------------------------------------------------------------
// Kernel 1: fused LN stats + fp16 convert. One warp per row.
// ---------------------------------------------------------------------------
__global__ __launch_bounds__(256)
void ln_convert_kernel(const float* __restrict__ x,
                       const float* __restrict__ gamma,
                       const float* __restrict__ beta) {
    __shared__ float gs[CC], bs[CC];
    const int tid = threadIdx.x;
    for (int i = tid; i < CC; i += 256) { gs[i] = gamma[i]; bs[i] = beta[i]; }
    __syncthreads();

    const int row  = blockIdx.x * 8 + (tid >> 5);
    const int lane = tid & 31;
    const float4* r = (const float4*)(x + (size_t)row * CC);
    float s = 0.f, ss = 0.f;
    #pragma unroll
    for (int i = lane; i < CC / 4; i += 32) {
        float4 v = r[i];
        s  += v.x + v.y + v.z + v.w;
        ss += v.x * v.x + v.y * v.y + v.z * v.z + v.w * v.w;
    }
    #pragma unroll
    for (int o = 16; o; o >>= 1) {
        s  += __shfl_xor_sync(0xffffffffu, s,  o);
        ss += __shfl_xor_sync(0xffffffffu, ss, o);
    }
    const float mu = s * (1.0f / CC);
    const float rs = rsqrtf(ss * (1.0f / CC) - mu * mu + 1e-5f);

    __half* ap = g_A + (size_t)row * CC;
    #pragma unroll
    for (int i = lane; i < CC / 4; i += 32) {
        float4 v = r[i];
        float y[4] = {v.x, v.y, v.z, v.w};
        union { __half h[4]; uint2 u; } hu;
        #pragma unroll
        for (int j = 0; j < 4; ++j)
            hu.h[j] = __float2half((y[j] - mu) * rs * gs[i * 4 + j] + bs[i * 4 + j]);
        *(uint2*)(ap + i * 4) = hu.u;
    }
}

// ---------------------------------------------------------------------------
// Kernel 2: W1 transpose + fp16 convert. out[n][k] = fp16(W1[k][n]).
// ---------------------------------------------------------------------------
__global__ __launch_bounds__(256)
void w1_convert_kernel(const float* __restrict__ W1) {
    __shared__ float t[32][33];
    const int tx = threadIdx.x, ty = threadIdx.y;    // 32x8
    const int bn = blockIdx.x * 32, bk = blockIdx.y * 32;
    #pragma unroll
    for (int i = 0; i < 4; ++i)
        t[ty + i * 8][tx] = W1[(size_t)(bk + ty + i * 8) * CC + bn + tx];
    __syncthreads();
    #pragma unroll
    for (int i = 0; i < 4; ++i) {
        const int n = bn + ty + i * 8, k = bk + tx;
        g_W1T[(size_t)n * CC + k] = __float2half(t[tx][ty + i * 8]);
    }
}

// ---------------------------------------------------------------------------
// Kernel 3: zero logits (placed 3rd so the GEMM lands in ncu's capture slot).
// ---------------------------------------------------------------------------
__global__ __launch_bounds__(256)
void zero_logits_kernel() {
    ((float4*)g_logits)[(size_t)blockIdx.x * 256 + threadIdx.x] =
        make_float4(0.f, 0.f, 0.f, 0.f);
}

// ---------------------------------------------------------------------------
// Kernel 4: fp16 mma.sync GEMM  logits += GELU(LN(x)@W1 + b1) @ W2
// CTA tile 128x128, 8 warps (4x2), warp 32x64, KC=64, 3-stage pipeline,
// 2 CTAs/SM. Rows of 128B; swizzle: seg ^= row&7.
// ---------------------------------------------------------------------------
#define KC      64
#define NCH     12                 // 768/64
#define TILE_B  16384              // 128 rows x 128 bytes
#define BUFSZ   (2 * TILE_B)       // A | B = 32KB
#define OFF_B   TILE_B
#define NSTAGE  3
#define SM_W2   (NSTAGE * BUFSZ)   // 98304
#define SM_B1   (SM_W2 + 4096)
#define SM_TOTAL (SM_B1 + 512 + 1024)

__device__ __forceinline__ uint32_t swz(int row, int seg) {
    return (uint32_t)(row * 128) + (uint32_t)(((seg ^ (row & 7)) & 7) << 4);
}

__device__ __forceinline__ void load_tile_cp(uint32_t dst, const __half* src,
                                             int tid) {
    // 128 rows x 64 fp16 (128B rows) = 1024 x 16B, 4 per thread
    #pragma unroll
    for (int j = 0; j < 4; ++j) {
        const int c = tid + j * 256;
        const int row = c >> 3, seg = c & 7;
        CP_ASYNC16(dst + swz(row, seg), src + (size_t)row * CC + seg * 8);
    }
}

__global__ __launch_bounds__(256, 2)
void gemm_kernel(const float* __restrict__ W2, const float* __restrict__ b1) {
    extern __shared__ __align__(16) char smraw[];
    const uint32_t sbraw = smem_to_u32(smraw);
    const uint32_t sb = (sbraw + 1023u) & ~1023u;
    char* sm = smraw + (sb - sbraw);
    float* W2s = (float*)(sm + SM_W2);
    float* b1s = (float*)(sm + SM_B1);

    const int tid = threadIdx.x;
    const int wid = tid >> 5;
    const int lid = tid & 31;
    const int warp_m = wid & 3;          // 4 along M
    const int warp_n = wid >> 2;         // 2 along N
    const int n0 = blockIdx.x * 128;
    const int r0 = blockIdx.y * 128;

    const __half* pA = g_A   + (size_t)r0 * CC;
    const __half* pB = g_W1T + (size_t)n0 * CC;

    for (int i = tid; i < 1024; i += 256) W2s[i] = W2[(size_t)n0 * KK + i];
    if (tid < 128) b1s[tid] = b1[n0 + tid];

    // prologue: stages 0, 1
    #pragma unroll
    for (int st = 0; st < 2; ++st) {
        const uint32_t bb = sb + st * BUFSZ;
        const int k0 = st * KC;
        load_tile_cp(bb,         pA + k0, tid);
        load_tile_cp(bb + OFF_B, pB + k0, tid);
        CP_COMMIT();
    }

    float acc[2][8][4];
    #pragma unroll
    for (int mf = 0; mf < 2; ++mf)
        #pragma unroll
        for (int nf = 0; nf < 8; ++nf)
            #pragma unroll
            for (int r = 0; r < 4; ++r) acc[mf][nf][r] = 0.f;

    const int a_row = warp_m * 32 + (lid & 15);                       // + mf*16
    const int a_seg = lid >> 4;                                       // + ks*2
    const int b_mat = lid >> 3;
    const int b_row = warp_n * 64 + ((b_mat >> 1) << 3) + (lid & 7);  // + np*16
    const int b_seg = b_mat & 1;                                      // + ks*2

    int stage = 0;
    for (int i = 0; i < NCH; ++i) {
        if (i < NCH - 1) CP_WAIT(1); else CP_WAIT(0);
        __syncthreads();

        // prefetch stage i+2 (overwrites buffer of stage i-1; safe after sync)
        if (i + 2 < NCH) {
            int st2 = stage + 2; if (st2 >= NSTAGE) st2 -= NSTAGE;
            const uint32_t bb = sb + st2 * BUFSZ;
            const int k0 = (i + 2) * KC;
            load_tile_cp(bb,         pA + k0, tid);
            load_tile_cp(bb + OFF_B, pB + k0, tid);
            CP_COMMIT();
        }

        const uint32_t bb = sb + stage * BUFSZ;
        #pragma unroll
        for (int ks = 0; ks < 4; ++ks) {
            uint32_t af[2][4];
            #pragma unroll
            for (int mf = 0; mf < 2; ++mf)
                ldsm_x4(af[mf], bb + swz(a_row + mf * 16, a_seg + ks * 2));
            #pragma unroll
            for (int np = 0; np < 4; ++np) {
                uint32_t bf[4];
                ldsm_x4(bf, bb + OFF_B + swz(b_row + np * 16, b_seg + ks * 2));
                #pragma unroll
                for (int mf = 0; mf < 2; ++mf) {
                    mma_f16(acc[mf][np * 2 + 0], af[mf], bf + 0);
                    mma_f16(acc[mf][np * 2 + 1], af[mf], bf + 2);
                }
            }
        }
        ++stage; if (stage == NSTAGE) stage = 0;
    }
    __syncthreads();

    // ---------------- Epilogue: +b1, GELU, fold W2, reduce ----------------
    float* logits_s = (float*)sm;        // reuse pipeline smem: 128x8 f32
    for (int i = tid; i < 1024; i += 256) logits_s[i] = 0.f;
    __syncthreads();

    const int qr = lid >> 2, qc = lid & 3;
    #pragma unroll
    for (int mf = 0; mf < 2; ++mf) {
        float lg[2][8];
        #pragma unroll
        for (int h = 0; h < 2; ++h)
            #pragma unroll
            for (int k = 0; k < 8; ++k) lg[h][k] = 0.f;

        #pragma unroll
        for (int nf = 0; nf < 8; ++nf) {
            const int colb = warp_n * 64 + nf * 8 + qc * 2;
            #pragma unroll
            for (int r = 0; r < 4; ++r) {
                const int c = colb + (r & 1);
                const float v = acc[mf][nf][r] + b1s[c];
                const float hh = gelu_exact(v);
                const float* w = &W2s[c * 8];
                float* l = lg[r >> 1];
                #pragma unroll
                for (int k = 0; k < 8; ++k) l[k] = fmaf(hh, w[k], l[k]);
            }
        }
        const int rA = warp_m * 32 + mf * 16 + qr;
        #pragma unroll
        for (int k = 0; k < 8; ++k) {
            atomicAdd(&logits_s[rA * 8 + k],       lg[0][k]);
            atomicAdd(&logits_s[(rA + 8) * 8 + k], lg[1][k]);
        }
    }
    __syncthreads();

    for (int i = tid; i < 1024; i += 256) {
        const int r = i >> 3, k = i & 7;
        atomicAdd(&g_logits[(size_t)(r0 + r) * KK + k], logits_s[i]);
    }
}

// ---------------------------------------------------------------------------
// Kernel 5: softmax stats per (b,k): row max and 1/sum(exp). No normalize pass.
// ---------------------------------------------------------------------------
__global__ __launch_bounds__(256)
void softmax_stats_kernel() {
    __shared__ float red[8];
    __shared__ float bcast;
    const int bk = blockIdx.x;
    const int b  = bk >> 3;
    const int kk = bk & 7;
    const int tid = threadIdx.x;
    const float* base = g_logits + (size_t)b * NN * KK + kk;

    float v[16];
    float mx = -1e30f;
    #pragma unroll
    for (int i = 0; i < 16; ++i) {
        v[i] = base[(size_t)(i * 256 + tid) * KK];
        mx = fmaxf(mx, v[i]);
    }
    #pragma unroll
    for (int o = 16; o; o >>= 1) mx = fmaxf(mx, __shfl_xor_sync(0xffffffffu, mx, o));
    if ((tid & 31) == 0) red[tid >> 5] = mx;
    __syncthreads();
    if (tid < 32) {
        float m = (tid < 8) ? red[tid] : -1e30f;
        #pragma unroll
        for (int o = 4; o; o >>= 1) m = fmaxf(m, __shfl_xor_sync(0xffffffffu, m, o));
        if (tid == 0) bcast = m;
    }
    __syncthreads();
    mx = bcast;

    float s = 0.f;
    #pragma unroll
    for (int i = 0; i < 16; ++i) s += __expf(v[i] - mx);
    #pragma unroll
    for (int o = 16; o; o >>= 1) s += __shfl_xor_sync(0xffffffffu, s, o);
    __syncthreads();
    if ((tid & 31) == 0) red[tid >> 5] = s;
    __syncthreads();
    if (tid < 32) {
        float t = (tid < 8) ? red[tid] : 0.f;
        #pragma unroll
        for (int o = 4; o; o >>= 1) t += __shfl_xor_sync(0xffffffffu, t, o);
        if (tid == 0) { g_mx[bk] = mx; g_inv[bk] = 1.0f / t; }
    }
}

// ---------------------------------------------------------------------------
// Kernel 6: out[b,k,c] = sum_n softmax(logits)[b,n,k] * x[b,n,c]
// exp-normalize applied while staging logits; MLP-8 x loads.
// ---------------------------------------------------------------------------
__global__ __launch_bounds__(256)
void pool_kernel(const float* __restrict__ x, float* __restrict__ out) {
    __shared__ float attn_s[512][8];     // 16 KB
    __shared__ float smx[8], sinv[8];
    const int nc = blockIdx.x;           // 0..7
    const int ct = blockIdx.y;           // 0..2
    const int b  = blockIdx.z;           // 0..31
    const int n0 = nc * 512;
    const int tid = threadIdx.x;

    if (tid < 8) { smx[tid] = g_mx[b * 8 + tid]; sinv[tid] = g_inv[b * 8 + tid]; }
    __syncthreads();

    const float* lp = g_logits + ((size_t)b * NN + n0) * KK;
    for (int i = tid; i < 512 * 8; i += 256) {
        const int k = i & 7;
        attn_s[i >> 3][k] = __expf(lp[i] - smx[k]) * sinv[k];
    }
    __syncthreads();

    const int c = ct * 256 + tid;
    const float* xp = x + ((size_t)b * NN + n0) * CC + c;
    float acc[8];
    #pragma unroll
    for (int kk = 0; kk < 8; ++kk) acc[kk] = 0.f;

    for (int nb = 0; nb < 512; nb += 8) {
        float xv[8];
        #pragma unroll
        for (int u = 0; u < 8; ++u)
            xv[u] = xp[(size_t)(nb + u) * CC];
        #pragma unroll
        for (int u = 0; u < 8; ++u) {
            float4 a0 = *(const float4*)(&attn_s[nb + u][0]);
            float4 a1 = *(const float4*)(&attn_s[nb + u][4]);
            acc[0] = fmaf(a0.x, xv[u], acc[0]);
            acc[1] = fmaf(a0.y, xv[u], acc[1]);
            acc[2] = fmaf(a0.z, xv[u], acc[2]);
            acc[3] = fmaf(a0.w, xv[u], acc[3]);
            acc[4] = fmaf(a1.x, xv[u], acc[4]);
            acc[5] = fmaf(a1.y, xv[u], acc[5]);
            acc[6] = fmaf(a1.z, xv[u], acc[6]);
            acc[7] = fmaf(a1.w, xv[u], acc[7]);
        }
    }
    #pragma unroll
    for (int kk = 0; kk < 8; ++kk)
        atomicAdd(&out[((size_t)b * KK + kk) * CC + c], acc[kk]);
}

// ---------------------------------------------------------------------------
extern "C" void kernel_launch(void* const* d_in, const int* in_sizes, int n_in,
                              void* d_out, int out_size) {
    const float* x     = (const float*)d_in[0];
    const float* gamma = (const float*)d_in[1];
    const float* beta  = (const float*)d_in[2];
    const float* W1    = (const float*)d_in[3];
    const float* b1    = (const float*)d_in[4];
    const float* W2    = (const float*)d_in[5];
    // b2 (d_in[6]) unused: constant over tokens -> cancels in softmax
    float* out = (float*)d_out;

    cudaMemsetAsync(out, 0, (size_t)out_size * sizeof(float));
    ln_convert_kernel<<<MM / 8, 256>>>(x, gamma, beta);                     // 1
    w1_convert_kernel<<<dim3(CC / 32, CC / 32), dim3(32, 8)>>>(W1);         // 2
    zero_logits_kernel<<<(MM * KK) / 1024, 256>>>();                        // 3
    cudaFuncSetAttribute(gemm_kernel, cudaFuncAttributeMaxDynamicSharedMemorySize, SM_TOTAL);
    gemm_kernel<<<dim3(6, MM / 128), 256, SM_TOTAL>>>(W2, b1);              // 4 (profiled)
    softmax_stats_kernel<<<BB * KK, 256>>>();                               // 5
    pool_kernel<<<dim3(8, 3, 32), 256>>>(x, out);                           // 6
}